// round 3
// baseline (speedup 1.0000x reference)
#include <cuda_runtime.h>
#include <math.h>

#define HW   65536
#define IMG  6291456          // 96*65536 (one batch image)
#define NPIX 25165824         // 4*96*65536
#define SCALE 0.17677669529663687f

typedef unsigned long long ull;

// Single-batch buffers, reused across the 4 batches (L2-resident pipeline).
// g_Q / g_K are reused as D0 / D1 scratch after attention has consumed them.
static __device__ __align__(16) float g_V[IMG];
static __device__ __align__(16) float g_aV[IMG];
static __device__ __align__(16) float g_Q[IMG];
static __device__ __align__(16) float g_K[IMG];
static __device__ __align__(16) float g_attn[IMG];
static __device__ float g_bias[3 * 64 * 64];

// ---- f32x2 packed helpers --------------------------------------------------
__device__ __forceinline__ ull pk(float x) {
    ull r; asm("mov.b64 %0, {%1, %1};" : "=l"(r) : "f"(x)); return r;
}
__device__ __forceinline__ ull pk2(float lo, float hi) {
    ull r; asm("mov.b64 %0, {%1, %2};" : "=l"(r) : "f"(lo), "f"(hi)); return r;
}
__device__ __forceinline__ ull fma2(ull a, ull b, ull c) {
    ull r; asm("fma.rn.f32x2 %0, %1, %2, %3;" : "=l"(r) : "l"(a), "l"(b), "l"(c)); return r;
}
__device__ __forceinline__ ull add2(ull a, ull b) {
    ull r; asm("add.rn.f32x2 %0, %1, %2;" : "=l"(r) : "l"(a), "l"(b)); return r;
}

// ---------------------------------------------------------------------------
// K1: relative-position bias MLP
// ---------------------------------------------------------------------------
__device__ __forceinline__ float sgnlog(int d) {
    float l = log1pf(fabsf((float)d));
    return d < 0 ? -l : l;
}

__global__ void bias_kernel(const float* __restrict__ mw1, const float* __restrict__ mb1,
                            const float* __restrict__ mw2, const float* __restrict__ mb2) {
    int t = blockIdx.x * 256 + threadIdx.x;
    if (t >= 4096) return;
    int i = t >> 6, j = t & 63;
    float r0 = sgnlog((i >> 3) - (j >> 3));
    float r1 = sgnlog((i & 7) - (j & 7));
    float a0 = 0.f, a1 = 0.f, a2 = 0.f;
    for (int h = 0; h < 256; h++) {
        float hid = fmaf(r0, mw1[h], fmaf(r1, mw1[256 + h], mb1[h]));
        hid = fmaxf(hid, 0.f);
        a0 = fmaf(hid, mw2[h * 3 + 0], a0);
        a1 = fmaf(hid, mw2[h * 3 + 1], a1);
        a2 = fmaf(hid, mw2[h * 3 + 2], a2);
    }
    g_bias[t]        = a0 + mb2[0];
    g_bias[4096 + t] = a1 + mb2[1];
    g_bias[8192 + t] = a2 + mb2[2];
}

// ---------------------------------------------------------------------------
// K2a: fused V/Q/K conv1x1 from one input-tile load; 3 weight phases.
// 512 blocks (128 px each), 256 threads, 16x16 blocking (6 outs x 4 pairs).
// smem: s_in2[96][66] ull + s_w[96][97] f + s_b[96] = 88320 B
// ---------------------------------------------------------------------------
__global__ __launch_bounds__(256, 2)
void conv3_kernel(const float* __restrict__ in,
                  const float* __restrict__ wv,  const float* __restrict__ bv,
                  const float* __restrict__ wqk, const float* __restrict__ bqk) {
    extern __shared__ char raw[];
    ull*   s_in2 = (ull*)raw;                 // 96*66
    float* s_w   = (float*)(raw + 6336 * 8);  // 96*97
    float* s_b   = s_w + 9312;
    int tid = threadIdx.x;
    int px0 = blockIdx.x << 7;
    const float* inb = in + px0;

    for (int l = tid; l < 6144; l += 256) {
        int c = l >> 6, p2 = l & 63;
        s_in2[c * 66 + p2] = *(const ull*)(inb + c * HW + 2 * p2);
    }

    const float* ws[3]; ws[0] = wv; ws[1] = wqk; ws[2] = wqk + 9216;
    const float* bs[3]; bs[0] = bv; bs[1] = bqk; bs[2] = bqk + 96;
    float* outs[3];     outs[0] = g_V; outs[1] = g_Q; outs[2] = g_K;
    float scl[3];       scl[0] = 1.f; scl[1] = SCALE; scl[2] = 1.f;

    int og = tid >> 4, pg = tid & 15;   // o = og+16u (u<6), pair = pg+16v (v<4)
    for (int ph = 0; ph < 3; ph++) {
        __syncthreads();   // previous phase done reading s_w (ph0: harmless)
        const float* w = ws[ph];
        for (int l = tid; l < 9216; l += 256) s_w[(l / 96) * 97 + (l % 96)] = w[l];
        if (tid < 96) s_b[tid] = bs[ph][tid];
        __syncthreads();

        ull acc[6][4];
        #pragma unroll
        for (int u = 0; u < 6; u++)
            #pragma unroll
            for (int v = 0; v < 4; v++) acc[u][v] = 0ull;

        #pragma unroll 4
        for (int c = 0; c < 96; c++) {
            ull w2[6], pf[4];
            #pragma unroll
            for (int u = 0; u < 6; u++) w2[u] = pk(s_w[(og + 16 * u) * 97 + c]);
            #pragma unroll
            for (int v = 0; v < 4; v++) pf[v] = s_in2[c * 66 + pg + 16 * v];
            #pragma unroll
            for (int u = 0; u < 6; u++)
                #pragma unroll
                for (int v = 0; v < 4; v++) acc[u][v] = fma2(w2[u], pf[v], acc[u][v]);
        }

        ull s2 = pk(scl[ph]);
        float* outb = outs[ph] + px0;
        #pragma unroll
        for (int u = 0; u < 6; u++) {
            int o = og + 16 * u;
            ull b2 = pk(s_b[o] * scl[ph]);
            ull* op = (ull*)(outb + o * HW);
            #pragma unroll
            for (int v = 0; v < 4; v++)
                op[pg + 16 * v] = fma2(acc[u][v], s2, b2);
        }
    }
}

// ---------------------------------------------------------------------------
// K2b: generic conv1x1, up to 2 jobs selected by blockIdx.z. 512 blocks/job.
// ---------------------------------------------------------------------------
struct ConvJob { const float* in; const float* w; const float* bias; float* out; float scale; };

__global__ __launch_bounds__(256, 2)
void conv_kernel(ConvJob j0, ConvJob j1) {
    ConvJob j = blockIdx.z ? j1 : j0;
    extern __shared__ char raw[];
    ull*   s_in2 = (ull*)raw;
    float* s_w   = (float*)(raw + 6336 * 8);
    float* s_b   = s_w + 9312;
    int tid = threadIdx.x;
    int px0 = blockIdx.x << 7;
    const float* inb = j.in + px0;
    float* outb = j.out + px0;

    for (int l = tid; l < 9216; l += 256) s_w[(l / 96) * 97 + (l % 96)] = j.w[l];
    if (tid < 96) s_b[tid] = j.bias[tid];
    for (int l = tid; l < 6144; l += 256) {
        int c = l >> 6, p2 = l & 63;
        s_in2[c * 66 + p2] = *(const ull*)(inb + c * HW + 2 * p2);
    }
    __syncthreads();

    int og = tid >> 4, pg = tid & 15;
    ull acc[6][4];
    #pragma unroll
    for (int u = 0; u < 6; u++)
        #pragma unroll
        for (int v = 0; v < 4; v++) acc[u][v] = 0ull;

    #pragma unroll 4
    for (int c = 0; c < 96; c++) {
        ull w2[6], pf[4];
        #pragma unroll
        for (int u = 0; u < 6; u++) w2[u] = pk(s_w[(og + 16 * u) * 97 + c]);
        #pragma unroll
        for (int v = 0; v < 4; v++) pf[v] = s_in2[c * 66 + pg + 16 * v];
        #pragma unroll
        for (int u = 0; u < 6; u++)
            #pragma unroll
            for (int v = 0; v < 4; v++) acc[u][v] = fma2(w2[u], pf[v], acc[u][v]);
    }

    ull s2 = pk(j.scale);
    #pragma unroll
    for (int u = 0; u < 6; u++) {
        int o = og + 16 * u;
        ull b2 = pk(s_b[o] * j.scale);
        ull* op = (ull*)(outb + o * HW);
        #pragma unroll
        for (int v = 0; v < 4; v++)
            op[pg + 16 * v] = fma2(acc[u][v], s2, b2);
    }
}

// ---------------------------------------------------------------------------
// K3: window attention, one block per (window, head). grid = 3072 per batch.
// ---------------------------------------------------------------------------
__global__ __launch_bounds__(256, 4)
void attn_kernel() {
    extern __shared__ float sm[];
    float* s_q  = sm;                       // s_q[n*33+d]
    ull*   s_kT = (ull*)(sm + 2112);        // s_kT[d*33+m2]
    ull*   s_v2 = (ull*)(sm + 4224);        // s_v2[m*33+d] = {v,v}
    float* s_s  = sm + 8448;                // s_s[n*66+m]
    ull*   s_p2 = (ull*)sm;                 // s_p2[m*33+n2]

    int tid = threadIdx.x;
    int blk = blockIdx.x;
    int h = blk % 3;
    int wid = blk / 3;
    int wy = wid >> 5, wx = wid & 31;
    int pixoff = wy * 2048 + wx * 8;
    const float* Qb = g_Q + pixoff + h * 32 * HW;
    const float* Kb = g_K + pixoff + h * 32 * HW;
    const float* Vb = g_V + pixoff + h * 32 * HW;

    for (int l = tid; l < 1024; l += 256) {
        int d = l >> 5, n2 = l & 31;
        int ga = d * HW + (n2 >> 2) * 256 + (n2 & 3) * 2;
        ull qv = *(const ull*)(Qb + ga);
        float2 q; asm("mov.b64 {%0, %1}, %2;" : "=f"(q.x), "=f"(q.y) : "l"(qv));
        s_q[(2 * n2) * 33 + d] = q.x;
        s_q[(2 * n2 + 1) * 33 + d] = q.y;
        s_kT[d * 33 + n2] = *(const ull*)(Kb + ga);
        ull vv = *(const ull*)(Vb + ga);
        float2 v; asm("mov.b64 {%0, %1}, %2;" : "=f"(v.x), "=f"(v.y) : "l"(vv));
        s_v2[(2 * n2) * 33 + d] = pk(v.x);
        s_v2[(2 * n2 + 1) * 33 + d] = pk(v.y);
    }
    __syncthreads();

    {   // S = Q K^T + bias
        int n0 = (tid >> 3) << 1, m2g = tid & 7;
        ull acc[2][4];
        #pragma unroll
        for (int i = 0; i < 2; i++)
            #pragma unroll
            for (int jj = 0; jj < 4; jj++) acc[i][jj] = 0ull;
        #pragma unroll 4
        for (int d = 0; d < 32; d++) {
            ull qa = pk(s_q[n0 * 33 + d]);
            ull qb = pk(s_q[n0 * 33 + 33 + d]);
            ull kd[4];
            #pragma unroll
            for (int jj = 0; jj < 4; jj++) kd[jj] = s_kT[d * 33 + m2g + 8 * jj];
            #pragma unroll
            for (int jj = 0; jj < 4; jj++) {
                acc[0][jj] = fma2(qa, kd[jj], acc[0][jj]);
                acc[1][jj] = fma2(qb, kd[jj], acc[1][jj]);
            }
        }
        const ull* bb = (const ull*)(g_bias + h * 4096);
        ull* ss = (ull*)s_s;
        #pragma unroll
        for (int i = 0; i < 2; i++) {
            int n = n0 + i;
            #pragma unroll
            for (int jj = 0; jj < 4; jj++) {
                int m2 = m2g + 8 * jj;
                ss[n * 33 + m2] = add2(acc[i][jj], bb[n * 32 + m2]);
            }
        }
    }
    __syncthreads();

    {   // softmax: 4 threads per row
        int row = tid >> 2, q4 = tid & 3;
        float* rp = s_s + row * 66 + q4 * 16;
        float e[16];
        float mx = rp[0];
        #pragma unroll
        for (int k = 1; k < 16; k++) mx = fmaxf(mx, rp[k]);
        mx = fmaxf(mx, __shfl_xor_sync(0xffffffffu, mx, 1));
        mx = fmaxf(mx, __shfl_xor_sync(0xffffffffu, mx, 2));
        float sum = 0.f;
        #pragma unroll
        for (int k = 0; k < 16; k++) { e[k] = __expf(rp[k] - mx); sum += e[k]; }
        sum += __shfl_xor_sync(0xffffffffu, sum, 1);
        sum += __shfl_xor_sync(0xffffffffu, sum, 2);
        float r = 1.f / sum;
        #pragma unroll
        for (int k = 0; k < 16; k++) rp[k] = e[k] * r;
    }
    __syncthreads();

    for (int l = tid; l < 2048; l += 256) {   // transpose-pack P
        int m = l >> 5, n2 = l & 31;
        s_p2[m * 33 + n2] = pk2(s_s[(2 * n2) * 66 + m], s_s[(2 * n2 + 1) * 66 + m]);
    }
    __syncthreads();

    {   // O = P V
        int n2 = tid >> 3, dg = tid & 7;
        ull acc[4];
        #pragma unroll
        for (int jj = 0; jj < 4; jj++) acc[jj] = 0ull;
        #pragma unroll 4
        for (int m = 0; m < 64; m++) {
            ull p2 = s_p2[m * 33 + n2];
            #pragma unroll
            for (int jj = 0; jj < 4; jj++)
                acc[jj] = fma2(p2, s_v2[m * 33 + dg + 8 * jj], acc[jj]);
        }
        int n0 = 2 * n2;
        float* ob = g_attn + pixoff + (n0 >> 3) * 256 + (n0 & 7);
        #pragma unroll
        for (int jj = 0; jj < 4; jj++) {
            int d = dg + 8 * jj;
            *(ull*)(ob + (h * 32 + d) * HW) = acc[jj];
        }
    }
}

// ---------------------------------------------------------------------------
// K4: depthwise 5x5 + bias + attn -> D (aliased onto g_Q / g_K). Per batch.
// grid = (16*96, 1, 2)
// ---------------------------------------------------------------------------
__global__ __launch_bounds__(256)
void dw_kernel(const float* __restrict__ wdw, const float* __restrict__ bdw,
               const float* __restrict__ wdwa, const float* __restrict__ bdwa) {
    extern __shared__ float st[];           // [20][264] + w[32]
    float* s_wd = st + 20 * 264;
    int z = blockIdx.z;
    const float* Vp = z ? g_aV : g_V;
    const float* wD = z ? wdwa : wdw;
    const float* bD = z ? bdwa : bdw;
    float* Dp = z ? g_K : g_Q;              // Q/K dead after attention

    int bx = blockIdx.x;               // 1536 = 16 * 96
    int yt = bx & 15;
    int c = bx >> 4;
    int y0 = yt << 4;
    int tid = threadIdx.x;
    const float* Vc = Vp + c * HW;

    for (int l = tid; l < 5200; l += 256) {
        int r = l / 260, q = l - r * 260;
        int yy = y0 + r - 2; yy = yy < 0 ? -yy : (yy > 255 ? 510 - yy : yy);
        int xx = q - 2;      xx = xx < 0 ? -xx : (xx > 255 ? 510 - xx : xx);
        st[r * 264 + q] = Vc[yy * 256 + xx];
    }
    if (tid < 25) s_wd[tid] = wD[c * 25 + tid];
    __syncthreads();

    float w[25];
    #pragma unroll
    for (int k = 0; k < 25; k++) w[k] = s_wd[k];
    float bias = __ldg(&bD[c]);

    int col = tid;
    float acc[16];
    #pragma unroll
    for (int r = 0; r < 16; r++) acc[r] = bias;

    #pragma unroll
    for (int rr = 0; rr < 20; rr++) {
        float xv[5];
        #pragma unroll
        for (int dx = 0; dx < 5; dx++) xv[dx] = st[rr * 264 + col + dx];
        #pragma unroll
        for (int dy = 0; dy < 5; dy++) {
            int r = rr - dy;
            if (r >= 0 && r < 16) {
                #pragma unroll
                for (int dx = 0; dx < 5; dx++)
                    acc[r] = fmaf(xv[dx], w[dy * 5 + dx], acc[r]);
            }
        }
    }

    const float* ab = g_attn + c * HW + y0 * 256 + col;
    float* db = Dp + c * HW + y0 * 256 + col;
    #pragma unroll
    for (int r = 0; r < 16; r++)
        db[r * 256] = acc[r] + ab[r * 256];
}

// ---------------------------------------------------------------------------
extern "C" void kernel_launch(void* const* d_in, const int* in_sizes, int n_in,
                              void* d_out, int out_size) {
    const float* vision     = (const float*)d_in[0];
    const float* ass_vision = (const float*)d_in[1];
    const float* wv   = (const float*)d_in[2];
    const float* bv   = (const float*)d_in[3];
    const float* wav  = (const float*)d_in[4];
    const float* bav  = (const float*)d_in[5];
    const float* wqk  = (const float*)d_in[6];
    const float* bqk  = (const float*)d_in[7];
    // d_in[8..9]: waqk/baqk dead (reference bug: aaw unused, ass_attn_out = attn_out)
    const float* wdw  = (const float*)d_in[10];
    const float* bdw  = (const float*)d_in[11];
    const float* wdwa = (const float*)d_in[12];
    const float* bdwa = (const float*)d_in[13];
    const float* wp   = (const float*)d_in[14];
    const float* bp   = (const float*)d_in[15];
    const float* wpa  = (const float*)d_in[16];
    const float* bpa  = (const float*)d_in[17];
    const float* mw1  = (const float*)d_in[18];
    const float* mb1  = (const float*)d_in[19];
    const float* mw2  = (const float*)d_in[20];
    const float* mb2  = (const float*)d_in[21];
    float* out = (float*)d_out;

    float *pV_unused, *paV, *pQ, *pK;
    cudaGetSymbolAddress((void**)&pV_unused, g_V);
    cudaGetSymbolAddress((void**)&paV, g_aV);
    cudaGetSymbolAddress((void**)&pQ,  g_Q);
    cudaGetSymbolAddress((void**)&pK,  g_K);

    const int SMEM_CONV = 6336 * 8 + 9312 * 4 + 96 * 4;   // 88320
    const int SMEM_ATTN = 12672 * 4;                       // 50688
    const int SMEM_DW   = (20 * 264 + 32) * 4;             // 21248
    cudaFuncSetAttribute(conv3_kernel, cudaFuncAttributeMaxDynamicSharedMemorySize, SMEM_CONV);
    cudaFuncSetAttribute(conv_kernel,  cudaFuncAttributeMaxDynamicSharedMemorySize, SMEM_CONV);
    cudaFuncSetAttribute(attn_kernel,  cudaFuncAttributeMaxDynamicSharedMemorySize, SMEM_ATTN);
    cudaFuncSetAttribute(dw_kernel,    cudaFuncAttributeMaxDynamicSharedMemorySize, SMEM_DW);

    bias_kernel<<<16, 256>>>(mw1, mb1, mw2, mb2);

    for (int b = 0; b < 4; b++) {
        // V, Q, K from one pass over vision_b
        conv3_kernel<<<512, 256, SMEM_CONV>>>(vision + b * IMG, wv, bv, wqk, bqk);

        // window attention (consumes Q, K, V)
        attn_kernel<<<3072, 256, SMEM_ATTN>>>();

        // aV projection (needed only by dw)
        ConvJob jaV = { ass_vision + b * IMG, wav, bav, paV, 1.0f };
        conv_kernel<<<dim3(512, 1, 1), 256, SMEM_CONV>>>(jaV, jaV);

        // depthwise + attn add -> D0 (in g_Q), D1 (in g_K)
        dw_kernel<<<dim3(1536, 1, 2), 256, SMEM_DW>>>(wdw, bdw, wdwa, bdwa);

        // final projections
        ConvJob jP0 = { pQ, wp,  bp,  out + b * IMG,        1.0f };
        ConvJob jP1 = { pK, wpa, bpa, out + NPIX + b * IMG, 1.0f };
        conv_kernel<<<dim3(512, 1, 2), 256, SMEM_CONV>>>(jP0, jP1);
    }
}

// round 4
// speedup vs baseline: 1.0083x; 1.0083x over previous
#include <cuda_runtime.h>
#include <math.h>

#define HW   65536
#define IMG  6291456          // 96*65536 (one batch image)
#define NPIX 25165824         // 4*96*65536
#define SCALE 0.17677669529663687f

typedef unsigned long long ull;

// Full-batch buffers. g_Q / g_K are reused as D0 / D1 scratch after attention.
static __device__ __align__(16) float g_V[NPIX];
static __device__ __align__(16) float g_aV[NPIX];
static __device__ __align__(16) float g_Q[NPIX];
static __device__ __align__(16) float g_K[NPIX];
static __device__ __align__(16) float g_attn[NPIX];
static __device__ float g_bias[3 * 64 * 64];

// ---- f32x2 packed helpers --------------------------------------------------
__device__ __forceinline__ ull pk(float x) {
    ull r; asm("mov.b64 %0, {%1, %1};" : "=l"(r) : "f"(x)); return r;
}
__device__ __forceinline__ ull pk2(float lo, float hi) {
    ull r; asm("mov.b64 %0, {%1, %2};" : "=l"(r) : "f"(lo), "f"(hi)); return r;
}
__device__ __forceinline__ ull fma2(ull a, ull b, ull c) {
    ull r; asm("fma.rn.f32x2 %0, %1, %2, %3;" : "=l"(r) : "l"(a), "l"(b), "l"(c)); return r;
}
__device__ __forceinline__ ull add2(ull a, ull b) {
    ull r; asm("add.rn.f32x2 %0, %1, %2;" : "=l"(r) : "l"(a), "l"(b)); return r;
}

// ---------------------------------------------------------------------------
// K1: relative-position bias MLP
// ---------------------------------------------------------------------------
__device__ __forceinline__ float sgnlog(int d) {
    float l = log1pf(fabsf((float)d));
    return d < 0 ? -l : l;
}

__global__ void bias_kernel(const float* __restrict__ mw1, const float* __restrict__ mb1,
                            const float* __restrict__ mw2, const float* __restrict__ mb2) {
    int t = blockIdx.x * 256 + threadIdx.x;
    if (t >= 4096) return;
    int i = t >> 6, j = t & 63;
    float r0 = sgnlog((i >> 3) - (j >> 3));
    float r1 = sgnlog((i & 7) - (j & 7));
    float a0 = 0.f, a1 = 0.f, a2 = 0.f;
    for (int h = 0; h < 256; h++) {
        float hid = fmaf(r0, mw1[h], fmaf(r1, mw1[256 + h], mb1[h]));
        hid = fmaxf(hid, 0.f);
        a0 = fmaf(hid, mw2[h * 3 + 0], a0);
        a1 = fmaf(hid, mw2[h * 3 + 1], a1);
        a2 = fmaf(hid, mw2[h * 3 + 2], a2);
    }
    g_bias[t]        = a0 + mb2[0];
    g_bias[4096 + t] = a1 + mb2[1];
    g_bias[8192 + t] = a2 + mb2[2];
}

// ---------------------------------------------------------------------------
// K2a: 4-phase conv1x1: V, Q, K from one vision-tile load; aV from ass_vision.
// grid 2048 (full batch), 256 threads, tile = 96 out x 128 px, 16x16 blocking.
// smem: s_in2[96][66] ull + s_w[96][97] f + s_b[96] = 88320 B
// ---------------------------------------------------------------------------
__global__ __launch_bounds__(256, 2)
void conv4_kernel(const float* __restrict__ vision, const float* __restrict__ avision,
                  const float* __restrict__ wv,  const float* __restrict__ bv,
                  const float* __restrict__ wqk, const float* __restrict__ bqk,
                  const float* __restrict__ wav, const float* __restrict__ bav) {
    extern __shared__ char raw[];
    ull*   s_in2 = (ull*)raw;                 // 96*66
    float* s_w   = (float*)(raw + 6336 * 8);  // 96*97
    float* s_b   = s_w + 9312;
    int tid = threadIdx.x;
    int bx = blockIdx.x;
    int b = bx >> 9, px0 = (bx & 511) << 7;
    int gbase = b * IMG + px0;

    const float* ws[4]; ws[0] = wv; ws[1] = wqk; ws[2] = wqk + 9216; ws[3] = wav;
    const float* bs[4]; bs[0] = bv; bs[1] = bqk; bs[2] = bqk + 96;   bs[3] = bav;
    float* outs[4];     outs[0] = g_V; outs[1] = g_Q; outs[2] = g_K; outs[3] = g_aV;
    float scl[4];       scl[0] = 1.f; scl[1] = SCALE; scl[2] = 1.f;  scl[3] = 1.f;

    int og = tid >> 4, pg = tid & 15;   // o = og+16u (u<6), pair = pg+16v (v<4)
    for (int ph = 0; ph < 4; ph++) {
        __syncthreads();   // previous phase done reading s_w / s_in2
        for (int l = tid; l < 9216; l += 256) s_w[(l / 96) * 97 + (l % 96)] = ws[ph][l];
        if (tid < 96) s_b[tid] = bs[ph][tid];
        if (ph == 0 || ph == 3) {
            const float* inb = (ph == 0 ? vision : avision) + gbase;
            for (int l = tid; l < 6144; l += 256) {
                int c = l >> 6, p2 = l & 63;
                s_in2[c * 66 + p2] = *(const ull*)(inb + c * HW + 2 * p2);
            }
        }
        __syncthreads();

        ull acc[6][4];
        #pragma unroll
        for (int u = 0; u < 6; u++)
            #pragma unroll
            for (int v = 0; v < 4; v++) acc[u][v] = 0ull;

        #pragma unroll 4
        for (int c = 0; c < 96; c++) {
            ull w2[6], pf[4];
            #pragma unroll
            for (int u = 0; u < 6; u++) w2[u] = pk(s_w[(og + 16 * u) * 97 + c]);
            #pragma unroll
            for (int v = 0; v < 4; v++) pf[v] = s_in2[c * 66 + pg + 16 * v];
            #pragma unroll
            for (int u = 0; u < 6; u++)
                #pragma unroll
                for (int v = 0; v < 4; v++) acc[u][v] = fma2(w2[u], pf[v], acc[u][v]);
        }

        ull s2 = pk(scl[ph]);
        float* outb = outs[ph] + gbase;
        #pragma unroll
        for (int u = 0; u < 6; u++) {
            int o = og + 16 * u;
            ull b2 = pk(s_b[o] * scl[ph]);
            ull* op = (ull*)(outb + o * HW);
            #pragma unroll
            for (int v = 0; v < 4; v++)
                op[pg + 16 * v] = fma2(acc[u][v], s2, b2);
        }
    }
}

// ---------------------------------------------------------------------------
// K2b: generic conv1x1, 2 jobs via blockIdx.z, grid (2048,1,2) full batch.
// ---------------------------------------------------------------------------
struct ConvJob { const float* in; const float* w; const float* bias; float* out; };

__global__ __launch_bounds__(256, 2)
void conv_kernel(ConvJob j0, ConvJob j1) {
    ConvJob j = blockIdx.z ? j1 : j0;
    extern __shared__ char raw[];
    ull*   s_in2 = (ull*)raw;
    float* s_w   = (float*)(raw + 6336 * 8);
    float* s_b   = s_w + 9312;
    int tid = threadIdx.x;
    int bx = blockIdx.x;
    int b = bx >> 9, px0 = (bx & 511) << 7;
    const float* inb = j.in + b * IMG + px0;
    float* outb = j.out + b * IMG + px0;

    for (int l = tid; l < 9216; l += 256) s_w[(l / 96) * 97 + (l % 96)] = j.w[l];
    if (tid < 96) s_b[tid] = j.bias[tid];
    for (int l = tid; l < 6144; l += 256) {
        int c = l >> 6, p2 = l & 63;
        s_in2[c * 66 + p2] = *(const ull*)(inb + c * HW + 2 * p2);
    }
    __syncthreads();

    int og = tid >> 4, pg = tid & 15;
    ull acc[6][4];
    #pragma unroll
    for (int u = 0; u < 6; u++)
        #pragma unroll
        for (int v = 0; v < 4; v++) acc[u][v] = 0ull;

    #pragma unroll 4
    for (int c = 0; c < 96; c++) {
        ull w2[6], pf[4];
        #pragma unroll
        for (int u = 0; u < 6; u++) w2[u] = pk(s_w[(og + 16 * u) * 97 + c]);
        #pragma unroll
        for (int v = 0; v < 4; v++) pf[v] = s_in2[c * 66 + pg + 16 * v];
        #pragma unroll
        for (int u = 0; u < 6; u++)
            #pragma unroll
            for (int v = 0; v < 4; v++) acc[u][v] = fma2(w2[u], pf[v], acc[u][v]);
    }

    #pragma unroll
    for (int u = 0; u < 6; u++) {
        int o = og + 16 * u;
        ull b2 = pk(s_b[o]);
        ull* op = (ull*)(outb + o * HW);
        #pragma unroll
        for (int v = 0; v < 4; v++)
            op[pg + 16 * v] = add2(acc[u][v], b2);
    }
}

// ---------------------------------------------------------------------------
// K3: window attention, one block per (window, head). grid = 12288 full batch.
// smem 50688 B, occupancy 4.
// ---------------------------------------------------------------------------
__global__ __launch_bounds__(256, 4)
void attn_kernel() {
    extern __shared__ float sm[];
    float* s_q  = sm;                       // s_q[n*33+d]
    ull*   s_kT = (ull*)(sm + 2112);        // s_kT[d*33+m2]
    ull*   s_v2 = (ull*)(sm + 4224);        // s_v2[m*33+d] = {v,v}
    float* s_s  = sm + 8448;                // s_s[n*66+m]
    ull*   s_p2 = (ull*)sm;                 // s_p2[m*33+n2]

    int tid = threadIdx.x;
    int blk = blockIdx.x;
    int h = blk % 3;
    int wid = blk / 3;
    int b = wid >> 10, wy = (wid >> 5) & 31, wx = wid & 31;
    int pixoff = b * IMG + wy * 2048 + wx * 8;
    const float* Qb = g_Q + pixoff + h * 32 * HW;
    const float* Kb = g_K + pixoff + h * 32 * HW;
    const float* Vb = g_V + pixoff + h * 32 * HW;

    for (int l = tid; l < 1024; l += 256) {
        int d = l >> 5, n2 = l & 31;
        int ga = d * HW + (n2 >> 2) * 256 + (n2 & 3) * 2;
        ull qv = *(const ull*)(Qb + ga);
        float2 q; asm("mov.b64 {%0, %1}, %2;" : "=f"(q.x), "=f"(q.y) : "l"(qv));
        s_q[(2 * n2) * 33 + d] = q.x;
        s_q[(2 * n2 + 1) * 33 + d] = q.y;
        s_kT[d * 33 + n2] = *(const ull*)(Kb + ga);
        ull vv = *(const ull*)(Vb + ga);
        float2 v; asm("mov.b64 {%0, %1}, %2;" : "=f"(v.x), "=f"(v.y) : "l"(vv));
        s_v2[(2 * n2) * 33 + d] = pk(v.x);
        s_v2[(2 * n2 + 1) * 33 + d] = pk(v.y);
    }
    __syncthreads();

    {   // S = Q K^T + bias
        int n0 = (tid >> 3) << 1, m2g = tid & 7;
        ull acc[2][4];
        #pragma unroll
        for (int i = 0; i < 2; i++)
            #pragma unroll
            for (int jj = 0; jj < 4; jj++) acc[i][jj] = 0ull;
        #pragma unroll 4
        for (int d = 0; d < 32; d++) {
            ull qa = pk(s_q[n0 * 33 + d]);
            ull qb = pk(s_q[n0 * 33 + 33 + d]);
            ull kd[4];
            #pragma unroll
            for (int jj = 0; jj < 4; jj++) kd[jj] = s_kT[d * 33 + m2g + 8 * jj];
            #pragma unroll
            for (int jj = 0; jj < 4; jj++) {
                acc[0][jj] = fma2(qa, kd[jj], acc[0][jj]);
                acc[1][jj] = fma2(qb, kd[jj], acc[1][jj]);
            }
        }
        const ull* bb = (const ull*)(g_bias + h * 4096);
        ull* ss = (ull*)s_s;
        #pragma unroll
        for (int i = 0; i < 2; i++) {
            int n = n0 + i;
            #pragma unroll
            for (int jj = 0; jj < 4; jj++) {
                int m2 = m2g + 8 * jj;
                ss[n * 33 + m2] = add2(acc[i][jj], bb[n * 32 + m2]);
            }
        }
    }
    __syncthreads();

    {   // softmax: 4 threads per row
        int row = tid >> 2, q4 = tid & 3;
        float* rp = s_s + row * 66 + q4 * 16;
        float e[16];
        float mx = rp[0];
        #pragma unroll
        for (int k = 1; k < 16; k++) mx = fmaxf(mx, rp[k]);
        mx = fmaxf(mx, __shfl_xor_sync(0xffffffffu, mx, 1));
        mx = fmaxf(mx, __shfl_xor_sync(0xffffffffu, mx, 2));
        float sum = 0.f;
        #pragma unroll
        for (int k = 0; k < 16; k++) { e[k] = __expf(rp[k] - mx); sum += e[k]; }
        sum += __shfl_xor_sync(0xffffffffu, sum, 1);
        sum += __shfl_xor_sync(0xffffffffu, sum, 2);
        float r = 1.f / sum;
        #pragma unroll
        for (int k = 0; k < 16; k++) rp[k] = e[k] * r;
    }
    __syncthreads();

    for (int l = tid; l < 2048; l += 256) {   // transpose-pack P
        int m = l >> 5, n2 = l & 31;
        s_p2[m * 33 + n2] = pk2(s_s[(2 * n2) * 66 + m], s_s[(2 * n2 + 1) * 66 + m]);
    }
    __syncthreads();

    {   // O = P V
        int n2 = tid >> 3, dg = tid & 7;
        ull acc[4];
        #pragma unroll
        for (int jj = 0; jj < 4; jj++) acc[jj] = 0ull;
        #pragma unroll 4
        for (int m = 0; m < 64; m++) {
            ull p2 = s_p2[m * 33 + n2];
            #pragma unroll
            for (int jj = 0; jj < 4; jj++)
                acc[jj] = fma2(p2, s_v2[m * 33 + dg + 8 * jj], acc[jj]);
        }
        int n0 = 2 * n2;
        float* ob = g_attn + pixoff + (n0 >> 3) * 256 + (n0 & 7);
        #pragma unroll
        for (int jj = 0; jj < 4; jj++) {
            int d = dg + 8 * jj;
            *(ull*)(ob + (h * 32 + d) * HW) = acc[jj];
        }
    }
}

// ---------------------------------------------------------------------------
// K4: fused-z depthwise 5x5 + bias + attn.
// One block computes BOTH D0 = dw(V)+attn (-> g_Q) and D1 = dw(aV)+attn (-> g_K)
// for one (b, c, 16-row tile). attn tile read once. grid = 6144.
// smem: 2*5280 + 64 = 10624 floats = 42496 B
// ---------------------------------------------------------------------------
__global__ __launch_bounds__(256)
void dw_kernel(const float* __restrict__ wdw, const float* __restrict__ bdw,
               const float* __restrict__ wdwa, const float* __restrict__ bdwa) {
    extern __shared__ float st[];
    float* s_h0 = st;                  // [20][264]
    float* s_h1 = st + 5280;           // [20][264]
    float* s_w0 = st + 10560;          // 25
    float* s_w1 = st + 10592;          // 25

    int bx = blockIdx.x;               // 6144 = 16 * 96 * 4
    int yt = bx & 15;
    int v = bx >> 4;
    int c = v % 96, b = v / 96;
    int y0 = yt << 4;
    int tid = threadIdx.x;
    int chan = b * IMG + c * HW;
    const float* Vc  = g_V  + chan;
    const float* aVc = g_aV + chan;

    for (int l = tid; l < 5200; l += 256) {
        int r = l / 260, q = l - r * 260;
        int yy = y0 + r - 2; yy = yy < 0 ? -yy : (yy > 255 ? 510 - yy : yy);
        int xx = q - 2;      xx = xx < 0 ? -xx : (xx > 255 ? 510 - xx : xx);
        int ga = yy * 256 + xx;
        s_h0[r * 264 + q] = Vc[ga];
        s_h1[r * 264 + q] = aVc[ga];
    }
    if (tid < 25) { s_w0[tid] = wdw[c * 25 + tid]; s_w1[tid] = wdwa[c * 25 + tid]; }
    __syncthreads();

    int col = tid;
    // attn tile, read once, used for both outputs
    float av[16];
    const float* ab = g_attn + chan + y0 * 256 + col;
    #pragma unroll
    for (int r = 0; r < 16; r++) av[r] = ab[r * 256];

    #pragma unroll
    for (int z = 0; z < 2; z++) {
        const float* sh = z ? s_h1 : s_h0;
        const float* sw = z ? s_w1 : s_w0;
        float bias = z ? __ldg(&bdwa[c]) : __ldg(&bdw[c]);
        float w[25];
        #pragma unroll
        for (int k = 0; k < 25; k++) w[k] = sw[k];

        float acc[16];
        #pragma unroll
        for (int r = 0; r < 16; r++) acc[r] = bias + av[r];

        #pragma unroll
        for (int rr = 0; rr < 20; rr++) {
            float xv[5];
            #pragma unroll
            for (int dx = 0; dx < 5; dx++) xv[dx] = sh[rr * 264 + col + dx];
            #pragma unroll
            for (int dy = 0; dy < 5; dy++) {
                int r = rr - dy;
                if (r >= 0 && r < 16) {
                    #pragma unroll
                    for (int dx = 0; dx < 5; dx++)
                        acc[r] = fmaf(xv[dx], w[dy * 5 + dx], acc[r]);
                }
            }
        }

        float* db = (z ? g_K : g_Q) + chan + y0 * 256 + col;
        #pragma unroll
        for (int r = 0; r < 16; r++)
            db[r * 256] = acc[r];
    }
}

// ---------------------------------------------------------------------------
extern "C" void kernel_launch(void* const* d_in, const int* in_sizes, int n_in,
                              void* d_out, int out_size) {
    const float* vision     = (const float*)d_in[0];
    const float* ass_vision = (const float*)d_in[1];
    const float* wv   = (const float*)d_in[2];
    const float* bv   = (const float*)d_in[3];
    const float* wav  = (const float*)d_in[4];
    const float* bav  = (const float*)d_in[5];
    const float* wqk  = (const float*)d_in[6];
    const float* bqk  = (const float*)d_in[7];
    // d_in[8..9]: waqk/baqk dead (reference bug: aaw unused, ass_attn_out = attn_out)
    const float* wdw  = (const float*)d_in[10];
    const float* bdw  = (const float*)d_in[11];
    const float* wdwa = (const float*)d_in[12];
    const float* bdwa = (const float*)d_in[13];
    const float* wp   = (const float*)d_in[14];
    const float* bp   = (const float*)d_in[15];
    const float* wpa  = (const float*)d_in[16];
    const float* bpa  = (const float*)d_in[17];
    const float* mw1  = (const float*)d_in[18];
    const float* mb1  = (const float*)d_in[19];
    const float* mw2  = (const float*)d_in[20];
    const float* mb2  = (const float*)d_in[21];
    float* out = (float*)d_out;

    float *pQ, *pK;
    cudaGetSymbolAddress((void**)&pQ, g_Q);
    cudaGetSymbolAddress((void**)&pK, g_K);

    const int SMEM_CONV = 6336 * 8 + 9312 * 4 + 96 * 4;   // 88320
    const int SMEM_ATTN = 12672 * 4;                       // 50688
    const int SMEM_DW   = 10624 * 4;                       // 42496
    cudaFuncSetAttribute(conv4_kernel, cudaFuncAttributeMaxDynamicSharedMemorySize, SMEM_CONV);
    cudaFuncSetAttribute(conv_kernel,  cudaFuncAttributeMaxDynamicSharedMemorySize, SMEM_CONV);
    cudaFuncSetAttribute(attn_kernel,  cudaFuncAttributeMaxDynamicSharedMemorySize, SMEM_ATTN);
    cudaFuncSetAttribute(dw_kernel,    cudaFuncAttributeMaxDynamicSharedMemorySize, SMEM_DW);

    bias_kernel<<<16, 256>>>(mw1, mb1, mw2, mb2);

    // V, Q, K, aV in one launch (vision/ass_vision each read once)
    conv4_kernel<<<2048, 256, SMEM_CONV>>>(vision, ass_vision, wv, bv, wqk, bqk, wav, bav);

    // window attention (consumes Q, K, V -> attn)
    attn_kernel<<<12288, 256, SMEM_ATTN>>>();

    // depthwise + attn add -> D0 (g_Q), D1 (g_K); attn read once per tile
    dw_kernel<<<6144, 256, SMEM_DW>>>(wdw, bdw, wdwa, bdwa);

    // final projections
    ConvJob jP0 = { pQ, wp,  bp,  out };
    ConvJob jP1 = { pK, wpa, bpa, out + NPIX };
    conv_kernel<<<dim3(2048, 1, 2), 256, SMEM_CONV>>>(jP0, jP1);
}

// round 5
// speedup vs baseline: 1.0184x; 1.0101x over previous
#include <cuda_runtime.h>
#include <math.h>

#define HW   65536
#define IMG  6291456          // 96*65536 (one batch image)
#define NPIX 25165824         // 4*96*65536
#define SCALE 0.17677669529663687f

typedef unsigned long long ull;

// Full-batch buffers. g_Q / g_K are reused as D0 / D1 scratch after attention.
static __device__ __align__(16) float g_V[NPIX];
static __device__ __align__(16) float g_aV[NPIX];
static __device__ __align__(16) float g_Q[NPIX];
static __device__ __align__(16) float g_K[NPIX];
static __device__ __align__(16) float g_attn[NPIX];
static __device__ float g_bias[3 * 64 * 64];

// ---- f32x2 packed helpers --------------------------------------------------
__device__ __forceinline__ ull pk(float x) {
    ull r; asm("mov.b64 %0, {%1, %1};" : "=l"(r) : "f"(x)); return r;
}
__device__ __forceinline__ ull pk2(float lo, float hi) {
    ull r; asm("mov.b64 %0, {%1, %2};" : "=l"(r) : "f"(lo), "f"(hi)); return r;
}
__device__ __forceinline__ ull fma2(ull a, ull b, ull c) {
    ull r; asm("fma.rn.f32x2 %0, %1, %2, %3;" : "=l"(r) : "l"(a), "l"(b), "l"(c)); return r;
}
__device__ __forceinline__ ull add2(ull a, ull b) {
    ull r; asm("add.rn.f32x2 %0, %1, %2;" : "=l"(r) : "l"(a), "l"(b)); return r;
}

// ---------------------------------------------------------------------------
// K1: relative-position bias MLP
// ---------------------------------------------------------------------------
__device__ __forceinline__ float sgnlog(int d) {
    float l = log1pf(fabsf((float)d));
    return d < 0 ? -l : l;
}

__global__ void bias_kernel(const float* __restrict__ mw1, const float* __restrict__ mb1,
                            const float* __restrict__ mw2, const float* __restrict__ mb2) {
    int t = blockIdx.x * 256 + threadIdx.x;
    if (t >= 4096) return;
    int i = t >> 6, j = t & 63;
    float r0 = sgnlog((i >> 3) - (j >> 3));
    float r1 = sgnlog((i & 7) - (j & 7));
    float a0 = 0.f, a1 = 0.f, a2 = 0.f;
    for (int h = 0; h < 256; h++) {
        float hid = fmaf(r0, mw1[h], fmaf(r1, mw1[256 + h], mb1[h]));
        hid = fmaxf(hid, 0.f);
        a0 = fmaf(hid, mw2[h * 3 + 0], a0);
        a1 = fmaf(hid, mw2[h * 3 + 1], a1);
        a2 = fmaf(hid, mw2[h * 3 + 2], a2);
    }
    g_bias[t]        = a0 + mb2[0];
    g_bias[4096 + t] = a1 + mb2[1];
    g_bias[8192 + t] = a2 + mb2[2];
}

// ---------------------------------------------------------------------------
// K2: conv1x1, half-output tiles for occupancy 3.
// grid (2048 px-tiles, 2 oc-halves, n_jobs). tile = 48 out x 128 px.
// smem: s_in2[96][66] ull (50688) + s_w[48][97] f (18624) + s_b[48] = 69504 B
// ---------------------------------------------------------------------------
struct ConvJob { const float* in; const float* w; const float* bias; float* out; float scale; };

__global__ __launch_bounds__(256, 3)
void conv_kernel(ConvJob j0, ConvJob j1, ConvJob j2, ConvJob j3) {
    ConvJob j = (blockIdx.z == 0) ? j0 : (blockIdx.z == 1) ? j1 : (blockIdx.z == 2) ? j2 : j3;
    extern __shared__ char raw[];
    ull*   s_in2 = (ull*)raw;                 // 96*66 ull
    float* s_w   = (float*)(raw + 6336 * 8);  // 48*97 f
    float* s_b   = s_w + 4656;                // 48
    int tid = threadIdx.x;
    int bx = blockIdx.x;
    int half = blockIdx.y;
    int b = bx >> 9, px0 = (bx & 511) << 7;
    const float* inb = j.in + b * IMG + px0;
    float* outb = j.out + b * IMG + px0;
    int o0 = half * 48;

    for (int l = tid; l < 4608; l += 256) {
        int r = l / 96, c = l - r * 96;
        s_w[r * 97 + c] = j.w[(o0 + r) * 96 + c];
    }
    if (tid < 48) s_b[tid] = j.bias[o0 + tid];
    for (int l = tid; l < 6144; l += 256) {
        int c = l >> 6, p2 = l & 63;
        s_in2[c * 66 + p2] = *(const ull*)(inb + c * HW + 2 * p2);
    }
    __syncthreads();

    int og = tid >> 4, pg = tid & 15;   // o = o0+og+16u (u<3), pair = pg+16v (v<4)
    ull acc[3][4];
    #pragma unroll
    for (int u = 0; u < 3; u++)
        #pragma unroll
        for (int v = 0; v < 4; v++) acc[u][v] = 0ull;

    #pragma unroll 4
    for (int c = 0; c < 96; c++) {
        ull w2[3], pf[4];
        #pragma unroll
        for (int u = 0; u < 3; u++) w2[u] = pk(s_w[(og + 16 * u) * 97 + c]);
        #pragma unroll
        for (int v = 0; v < 4; v++) pf[v] = s_in2[c * 66 + pg + 16 * v];
        #pragma unroll
        for (int u = 0; u < 3; u++)
            #pragma unroll
            for (int v = 0; v < 4; v++) acc[u][v] = fma2(w2[u], pf[v], acc[u][v]);
    }

    ull s2 = pk(j.scale);
    #pragma unroll
    for (int u = 0; u < 3; u++) {
        int o = o0 + og + 16 * u;
        ull b2 = pk(s_b[og + 16 * u] * j.scale);
        ull* op = (ull*)(outb + o * HW);
        #pragma unroll
        for (int v = 0; v < 4; v++)
            op[pg + 16 * v] = fma2(acc[u][v], s2, b2);
    }
}

// ---------------------------------------------------------------------------
// K3: window attention, one block per (window, head). grid = 12288 full batch.
// smem 50688 B, occupancy 4.
// ---------------------------------------------------------------------------
__global__ __launch_bounds__(256, 4)
void attn_kernel() {
    extern __shared__ float sm[];
    float* s_q  = sm;                       // s_q[n*33+d]
    ull*   s_kT = (ull*)(sm + 2112);        // s_kT[d*33+m2]
    ull*   s_v2 = (ull*)(sm + 4224);        // s_v2[m*33+d] = {v,v}
    float* s_s  = sm + 8448;                // s_s[n*66+m]
    ull*   s_p2 = (ull*)sm;                 // s_p2[m*33+n2]

    int tid = threadIdx.x;
    int blk = blockIdx.x;
    int h = blk % 3;
    int wid = blk / 3;
    int b = wid >> 10, wy = (wid >> 5) & 31, wx = wid & 31;
    int pixoff = b * IMG + wy * 2048 + wx * 8;
    const float* Qb = g_Q + pixoff + h * 32 * HW;
    const float* Kb = g_K + pixoff + h * 32 * HW;
    const float* Vb = g_V + pixoff + h * 32 * HW;

    for (int l = tid; l < 1024; l += 256) {
        int d = l >> 5, n2 = l & 31;
        int ga = d * HW + (n2 >> 2) * 256 + (n2 & 3) * 2;
        ull qv = *(const ull*)(Qb + ga);
        float2 q; asm("mov.b64 {%0, %1}, %2;" : "=f"(q.x), "=f"(q.y) : "l"(qv));
        s_q[(2 * n2) * 33 + d] = q.x;
        s_q[(2 * n2 + 1) * 33 + d] = q.y;
        s_kT[d * 33 + n2] = *(const ull*)(Kb + ga);
        ull vv = *(const ull*)(Vb + ga);
        float2 v; asm("mov.b64 {%0, %1}, %2;" : "=f"(v.x), "=f"(v.y) : "l"(vv));
        s_v2[(2 * n2) * 33 + d] = pk(v.x);
        s_v2[(2 * n2 + 1) * 33 + d] = pk(v.y);
    }
    __syncthreads();

    {   // S = Q K^T + bias
        int n0 = (tid >> 3) << 1, m2g = tid & 7;
        ull acc[2][4];
        #pragma unroll
        for (int i = 0; i < 2; i++)
            #pragma unroll
            for (int jj = 0; jj < 4; jj++) acc[i][jj] = 0ull;
        #pragma unroll 4
        for (int d = 0; d < 32; d++) {
            ull qa = pk(s_q[n0 * 33 + d]);
            ull qb = pk(s_q[n0 * 33 + 33 + d]);
            ull kd[4];
            #pragma unroll
            for (int jj = 0; jj < 4; jj++) kd[jj] = s_kT[d * 33 + m2g + 8 * jj];
            #pragma unroll
            for (int jj = 0; jj < 4; jj++) {
                acc[0][jj] = fma2(qa, kd[jj], acc[0][jj]);
                acc[1][jj] = fma2(qb, kd[jj], acc[1][jj]);
            }
        }
        const ull* bb = (const ull*)(g_bias + h * 4096);
        ull* ss = (ull*)s_s;
        #pragma unroll
        for (int i = 0; i < 2; i++) {
            int n = n0 + i;
            #pragma unroll
            for (int jj = 0; jj < 4; jj++) {
                int m2 = m2g + 8 * jj;
                ss[n * 33 + m2] = add2(acc[i][jj], bb[n * 32 + m2]);
            }
        }
    }
    __syncthreads();

    {   // softmax: 4 threads per row
        int row = tid >> 2, q4 = tid & 3;
        float* rp = s_s + row * 66 + q4 * 16;
        float e[16];
        float mx = rp[0];
        #pragma unroll
        for (int k = 1; k < 16; k++) mx = fmaxf(mx, rp[k]);
        mx = fmaxf(mx, __shfl_xor_sync(0xffffffffu, mx, 1));
        mx = fmaxf(mx, __shfl_xor_sync(0xffffffffu, mx, 2));
        float sum = 0.f;
        #pragma unroll
        for (int k = 0; k < 16; k++) { e[k] = __expf(rp[k] - mx); sum += e[k]; }
        sum += __shfl_xor_sync(0xffffffffu, sum, 1);
        sum += __shfl_xor_sync(0xffffffffu, sum, 2);
        float r = 1.f / sum;
        #pragma unroll
        for (int k = 0; k < 16; k++) rp[k] = e[k] * r;
    }
    __syncthreads();

    for (int l = tid; l < 2048; l += 256) {   // transpose-pack P
        int m = l >> 5, n2 = l & 31;
        s_p2[m * 33 + n2] = pk2(s_s[(2 * n2) * 66 + m], s_s[(2 * n2 + 1) * 66 + m]);
    }
    __syncthreads();

    {   // O = P V
        int n2 = tid >> 3, dg = tid & 7;
        ull acc[4];
        #pragma unroll
        for (int jj = 0; jj < 4; jj++) acc[jj] = 0ull;
        #pragma unroll 4
        for (int m = 0; m < 64; m++) {
            ull p2 = s_p2[m * 33 + n2];
            #pragma unroll
            for (int jj = 0; jj < 4; jj++)
                acc[jj] = fma2(p2, s_v2[m * 33 + dg + 8 * jj], acc[jj]);
        }
        int n0 = 2 * n2;
        float* ob = g_attn + pixoff + (n0 >> 3) * 256 + (n0 & 7);
        #pragma unroll
        for (int jj = 0; jj < 4; jj++) {
            int d = dg + 8 * jj;
            *(ull*)(ob + (h * 32 + d) * HW) = acc[jj];
        }
    }
}

// ---------------------------------------------------------------------------
// K4: fused-z depthwise 5x5 + bias + attn (attn tile read once).
// D0 = dw(V)+attn -> g_Q, D1 = dw(aV)+attn -> g_K. grid = 6144.
// smem: 2*5280 + 64 = 10624 floats = 42496 B
// ---------------------------------------------------------------------------
__global__ __launch_bounds__(256)
void dw_kernel(const float* __restrict__ wdw, const float* __restrict__ bdw,
               const float* __restrict__ wdwa, const float* __restrict__ bdwa) {
    extern __shared__ float st[];
    float* s_h0 = st;                  // [20][264]
    float* s_h1 = st + 5280;           // [20][264]
    float* s_w0 = st + 10560;          // 25
    float* s_w1 = st + 10592;          // 25

    int bx = blockIdx.x;               // 6144 = 16 * 96 * 4
    int yt = bx & 15;
    int v = bx >> 4;
    int c = v % 96, b = v / 96;
    int y0 = yt << 4;
    int tid = threadIdx.x;
    int chan = b * IMG + c * HW;
    const float* Vc  = g_V  + chan;
    const float* aVc = g_aV + chan;

    for (int l = tid; l < 5200; l += 256) {
        int r = l / 260, q = l - r * 260;
        int yy = y0 + r - 2; yy = yy < 0 ? -yy : (yy > 255 ? 510 - yy : yy);
        int xx = q - 2;      xx = xx < 0 ? -xx : (xx > 255 ? 510 - xx : xx);
        int ga = yy * 256 + xx;
        s_h0[r * 264 + q] = Vc[ga];
        s_h1[r * 264 + q] = aVc[ga];
    }
    if (tid < 25) { s_w0[tid] = wdw[c * 25 + tid]; s_w1[tid] = wdwa[c * 25 + tid]; }
    __syncthreads();

    int col = tid;
    float av[16];
    const float* ab = g_attn + chan + y0 * 256 + col;
    #pragma unroll
    for (int r = 0; r < 16; r++) av[r] = ab[r * 256];

    #pragma unroll
    for (int z = 0; z < 2; z++) {
        const float* sh = z ? s_h1 : s_h0;
        const float* sw = z ? s_w1 : s_w0;
        float bias = z ? __ldg(&bdwa[c]) : __ldg(&bdw[c]);
        float w[25];
        #pragma unroll
        for (int k = 0; k < 25; k++) w[k] = sw[k];

        float acc[16];
        #pragma unroll
        for (int r = 0; r < 16; r++) acc[r] = bias + av[r];

        #pragma unroll
        for (int rr = 0; rr < 20; rr++) {
            float xv[5];
            #pragma unroll
            for (int dx = 0; dx < 5; dx++) xv[dx] = sh[rr * 264 + col + dx];
            #pragma unroll
            for (int dy = 0; dy < 5; dy++) {
                int r = rr - dy;
                if (r >= 0 && r < 16) {
                    #pragma unroll
                    for (int dx = 0; dx < 5; dx++)
                        acc[r] = fmaf(xv[dx], w[dy * 5 + dx], acc[r]);
                }
            }
        }

        float* db = (z ? g_K : g_Q) + chan + y0 * 256 + col;
        #pragma unroll
        for (int r = 0; r < 16; r++)
            db[r * 256] = acc[r];
    }
}

// ---------------------------------------------------------------------------
extern "C" void kernel_launch(void* const* d_in, const int* in_sizes, int n_in,
                              void* d_out, int out_size) {
    const float* vision     = (const float*)d_in[0];
    const float* ass_vision = (const float*)d_in[1];
    const float* wv   = (const float*)d_in[2];
    const float* bv   = (const float*)d_in[3];
    const float* wav  = (const float*)d_in[4];
    const float* bav  = (const float*)d_in[5];
    const float* wqk  = (const float*)d_in[6];
    const float* bqk  = (const float*)d_in[7];
    // d_in[8..9]: waqk/baqk dead (reference bug: aaw unused, ass_attn_out = attn_out)
    const float* wdw  = (const float*)d_in[10];
    const float* bdw  = (const float*)d_in[11];
    const float* wdwa = (const float*)d_in[12];
    const float* bdwa = (const float*)d_in[13];
    const float* wp   = (const float*)d_in[14];
    const float* bp   = (const float*)d_in[15];
    const float* wpa  = (const float*)d_in[16];
    const float* bpa  = (const float*)d_in[17];
    const float* mw1  = (const float*)d_in[18];
    const float* mb1  = (const float*)d_in[19];
    const float* mw2  = (const float*)d_in[20];
    const float* mb2  = (const float*)d_in[21];
    float* out = (float*)d_out;

    float *pV, *paV, *pQ, *pK;
    cudaGetSymbolAddress((void**)&pV,  g_V);
    cudaGetSymbolAddress((void**)&paV, g_aV);
    cudaGetSymbolAddress((void**)&pQ,  g_Q);
    cudaGetSymbolAddress((void**)&pK,  g_K);

    const int SMEM_CONV = 6336 * 8 + 4656 * 4 + 48 * 4;   // 69504
    const int SMEM_ATTN = 12672 * 4;                       // 50688
    const int SMEM_DW   = 10624 * 4;                       // 42496
    cudaFuncSetAttribute(conv_kernel, cudaFuncAttributeMaxDynamicSharedMemorySize, SMEM_CONV);
    cudaFuncSetAttribute(attn_kernel, cudaFuncAttributeMaxDynamicSharedMemorySize, SMEM_ATTN);
    cudaFuncSetAttribute(dw_kernel,   cudaFuncAttributeMaxDynamicSharedMemorySize, SMEM_DW);

    bias_kernel<<<16, 256>>>(mw1, mb1, mw2, mb2);

    // V, Q, K, aV: 4 independent jobs x 2 oc-halves x 2048 px-tiles
    ConvJob jV  = { vision,     wv,         bv,       pV,  1.0f };
    ConvJob jQ  = { vision,     wqk,        bqk,      pQ,  SCALE };
    ConvJob jK  = { vision,     wqk + 9216, bqk + 96, pK,  1.0f };
    ConvJob jaV = { ass_vision, wav,        bav,      paV, 1.0f };
    conv_kernel<<<dim3(2048, 2, 4), 256, SMEM_CONV>>>(jV, jQ, jK, jaV);

    // window attention (consumes Q, K, V -> attn)
    attn_kernel<<<12288, 256, SMEM_ATTN>>>();

    // depthwise + attn add -> D0 (g_Q), D1 (g_K)
    dw_kernel<<<6144, 256, SMEM_DW>>>(wdw, bdw, wdwa, bdwa);

    // final projections (2 jobs x 2 halves)
    ConvJob jP0 = { pQ, wp,  bp,  out,        1.0f };
    ConvJob jP1 = { pK, wpa, bpa, out + NPIX, 1.0f };
    conv_kernel<<<dim3(2048, 2, 2), 256, SMEM_CONV>>>(jP0, jP1, jP0, jP0);
}

// round 6
// speedup vs baseline: 1.1827x; 1.1613x over previous
#include <cuda_runtime.h>
#include <math.h>

#define HW   65536
#define IMG  6291456          // 96*65536
#define NPIX 25165824         // 4*96*65536
#define SCALE 0.17677669529663687f

typedef unsigned long long ull;

// Full-batch buffers. g_Q / g_K are reused as D0 / D1 scratch after attention.
static __device__ __align__(16) float g_V[NPIX];
static __device__ __align__(16) float g_aV[NPIX];
static __device__ __align__(16) float g_Q[NPIX];
static __device__ __align__(16) float g_K[NPIX];
static __device__ __align__(16) float g_attn[NPIX];
static __device__ __align__(16) float g_bias[3 * 64 * 64];

// ---- f32x2 packed helpers --------------------------------------------------
__device__ __forceinline__ ull pk(float x) {
    ull r; asm("mov.b64 %0, {%1, %1};" : "=l"(r) : "f"(x)); return r;
}
__device__ __forceinline__ float2 upk(ull v) {
    float2 f; asm("mov.b64 {%0, %1}, %2;" : "=f"(f.x), "=f"(f.y) : "l"(v)); return f;
}
__device__ __forceinline__ ull fma2(ull a, ull b, ull c) {
    ull r; asm("fma.rn.f32x2 %0, %1, %2, %3;" : "=l"(r) : "l"(a), "l"(b), "l"(c)); return r;
}
__device__ __forceinline__ ull mul2(ull a, ull b) {
    ull r; asm("mul.rn.f32x2 %0, %1, %2;" : "=l"(r) : "l"(a), "l"(b)); return r;
}
__device__ __forceinline__ ull add2(ull a, ull b) {
    ull r; asm("add.rn.f32x2 %0, %1, %2;" : "=l"(r) : "l"(a), "l"(b)); return r;
}

// ---------------------------------------------------------------------------
// K1: relative-position bias MLP
// ---------------------------------------------------------------------------
__device__ __forceinline__ float sgnlog(int d) {
    float l = log1pf(fabsf((float)d));
    return d < 0 ? -l : l;
}

__global__ void bias_kernel(const float* __restrict__ mw1, const float* __restrict__ mb1,
                            const float* __restrict__ mw2, const float* __restrict__ mb2) {
    int t = blockIdx.x * 256 + threadIdx.x;
    if (t >= 4096) return;
    int i = t >> 6, j = t & 63;
    float r0 = sgnlog((i >> 3) - (j >> 3));
    float r1 = sgnlog((i & 7) - (j & 7));
    float a0 = 0.f, a1 = 0.f, a2 = 0.f;
    for (int h = 0; h < 256; h++) {
        float hid = fmaf(r0, mw1[h], fmaf(r1, mw1[256 + h], mb1[h]));
        hid = fmaxf(hid, 0.f);
        a0 = fmaf(hid, mw2[h * 3 + 0], a0);
        a1 = fmaf(hid, mw2[h * 3 + 1], a1);
        a2 = fmaf(hid, mw2[h * 3 + 2], a2);
    }
    g_bias[t]        = a0 + mb2[0];
    g_bias[4096 + t] = a1 + mb2[1];
    g_bias[8192 + t] = a2 + mb2[2];
}

// ---------------------------------------------------------------------------
// K2: conv1x1 96->96 (round-2 shape: 96 out x 128 px, acc[3][8], occ 2).
// smem: s_in2[96][66] ull (50688) + s_w[96][97] f (37248) + s_b[96] = 88320 B
// ---------------------------------------------------------------------------
struct ConvJob { const float* in; const float* w; const float* bias; float* out; float scale; };

__global__ __launch_bounds__(256, 2)
void conv_kernel(ConvJob j0, ConvJob j1, ConvJob j2, ConvJob j3) {
    ConvJob j = (blockIdx.z == 0) ? j0 : (blockIdx.z == 1) ? j1 : (blockIdx.z == 2) ? j2 : j3;
    extern __shared__ char raw[];
    ull*   s_in2 = (ull*)raw;                 // 96*66 ull
    float* s_w   = (float*)(raw + 6336 * 8);  // 96*97 f
    float* s_b   = s_w + 9312;                // 96
    int tid = threadIdx.x;
    int bx = blockIdx.x;
    int b = bx >> 9, px0 = (bx & 511) << 7;
    const float* inb = j.in + b * IMG + px0;
    float* outb = j.out + b * IMG + px0;

    for (int l = tid; l < 9216; l += 256) s_w[(l / 96) * 97 + (l % 96)] = j.w[l];
    if (tid < 96) s_b[tid] = j.bias[tid];
    for (int l = tid; l < 6144; l += 256) {
        int c = l >> 6, p2 = l & 63;
        s_in2[c * 66 + p2] = *(const ull*)(inb + c * HW + 2 * p2);
    }
    __syncthreads();

    int og = tid >> 3, pg = tid & 7;   // o = og+32u (u<3); pair = pg+8v (v<8)
    ull acc[3][8];
    #pragma unroll
    for (int u = 0; u < 3; u++)
        #pragma unroll
        for (int v = 0; v < 8; v++) acc[u][v] = 0ull;

    #pragma unroll 4
    for (int c = 0; c < 96; c++) {
        ull w2[3], pf[8];
        #pragma unroll
        for (int u = 0; u < 3; u++) w2[u] = pk(s_w[(og + 32 * u) * 97 + c]);
        #pragma unroll
        for (int v = 0; v < 8; v++) pf[v] = s_in2[c * 66 + pg + 8 * v];
        #pragma unroll
        for (int u = 0; u < 3; u++)
            #pragma unroll
            for (int v = 0; v < 8; v++) acc[u][v] = fma2(w2[u], pf[v], acc[u][v]);
    }

    ull s2 = pk(j.scale);
    #pragma unroll
    for (int u = 0; u < 3; u++) {
        int o = og + 32 * u;
        ull b2 = pk(s_b[o] * j.scale);
        ull* op = (ull*)(outb + o * HW);
        #pragma unroll
        for (int v = 0; v < 8; v++)
            op[pg + 8 * v] = fma2(acc[u][v], s2, b2);
    }
}

// ---------------------------------------------------------------------------
// K3: window attention — one thread per (head, row). Block = 192 threads =
// 1 window x 3 heads x 64 rows. One barrier. S-row / P / O in registers.
// smem floats: s_q[3][64*33] (0..6336) | s_k ull[3][32*33] (f-off 6336..12672)
//              | s_v[3][64*34] (12672..19200).  Total 76800 B.
// ---------------------------------------------------------------------------
__global__ __launch_bounds__(192, 2)
void attn_kernel() {
    extern __shared__ float sm[];
    float* s_q = sm;                      // [h][n*33+d]
    ull*   s_k = (ull*)(sm + 6336);       // [h][d*33+m2], pair over m
    float* s_v = sm + 12672;              // [h][m*34+d]

    int tid = threadIdx.x;
    int blk = blockIdx.x;
    int b = blk >> 10, wy = (blk >> 5) & 31, wx = blk & 31;
    int pixoff = b * IMG + wy * 2048 + wx * 8;

    // ---- load Q/K/V for all 3 heads: 3072 iters = 192 threads x 16 ----
    for (int l = tid; l < 3072; l += 192) {
        int hh = l >> 10;
        int r = l & 1023;
        int d = r >> 5, n2 = r & 31;
        int ga = pixoff + (hh * 32 + d) * HW + (n2 >> 2) * 256 + (n2 & 3) * 2;
        float2 q = upk(*(const ull*)(g_Q + ga));
        s_q[hh * 2112 + (2 * n2) * 33 + d] = q.x;
        s_q[hh * 2112 + (2 * n2 + 1) * 33 + d] = q.y;
        s_k[hh * 1056 + d * 33 + n2] = *(const ull*)(g_K + ga);
        float2 v = upk(*(const ull*)(g_V + ga));
        s_v[hh * 2176 + (2 * n2) * 34 + d] = v.x;
        s_v[hh * 2176 + (2 * n2 + 1) * 34 + d] = v.y;
    }
    __syncthreads();

    int h = tid >> 6, n = tid & 63;
    const float* qrow = s_q + h * 2112 + n * 33;
    const ull*   kh   = s_k + h * 1056;
    const float* vh   = s_v + h * 2176;

    // ---- S row = q . K^T + bias (bias as accumulator init) ----
    ull acc[32];
    {
        const ull* bias2 = (const ull*)(g_bias + h * 4096 + n * 64);
        #pragma unroll
        for (int m2 = 0; m2 < 32; m2++) acc[m2] = bias2[m2];
    }
    #pragma unroll 4
    for (int d = 0; d < 32; d++) {
        ull qd = pk(qrow[d]);
        const ull* krow = kh + d * 33;
        #pragma unroll
        for (int m2 = 0; m2 < 32; m2++) acc[m2] = fma2(qd, krow[m2], acc[m2]);
    }

    // ---- softmax over the 64 register-resident scores ----
    float p[64];
    #pragma unroll
    for (int m2 = 0; m2 < 32; m2++) {
        float2 f = upk(acc[m2]);
        p[2 * m2] = f.x; p[2 * m2 + 1] = f.y;
    }
    float mx = p[0];
    #pragma unroll
    for (int k = 1; k < 64; k++) mx = fmaxf(mx, p[k]);
    float sum = 0.f;
    #pragma unroll
    for (int k = 0; k < 64; k++) { p[k] = __expf(p[k] - mx); sum += p[k]; }
    float rinv = 1.f / sum;

    // ---- O row = (1/sum) * p . V ----
    ull oacc[16];
    #pragma unroll
    for (int d2 = 0; d2 < 16; d2++) oacc[d2] = 0ull;
    #pragma unroll
    for (int m = 0; m < 64; m++) {
        ull pm = pk(p[m]);
        const float* vrow = vh + m * 34;
        #pragma unroll
        for (int d2 = 0; d2 < 16; d2++)
            oacc[d2] = fma2(pm, *(const ull*)(vrow + 2 * d2), oacc[d2]);
    }
    ull rr = pk(rinv);
    float* ob = g_attn + pixoff + (n >> 3) * 256 + (n & 7);
    #pragma unroll
    for (int d2 = 0; d2 < 16; d2++) {
        float2 f = upk(mul2(oacc[d2], rr));
        ob[(h * 32 + 2 * d2) * HW] = f.x;
        ob[(h * 32 + 2 * d2 + 1) * HW] = f.y;
    }
}

// ---------------------------------------------------------------------------
// K4: fused-z depthwise 5x5 + bias + attn (attn tile read once).
// D0 = dw(V)+attn -> g_Q, D1 = dw(aV)+attn -> g_K. grid = 6144.
// ---------------------------------------------------------------------------
__global__ __launch_bounds__(256)
void dw_kernel(const float* __restrict__ wdw, const float* __restrict__ bdw,
               const float* __restrict__ wdwa, const float* __restrict__ bdwa) {
    extern __shared__ float st[];
    float* s_h0 = st;                  // [20][264]
    float* s_h1 = st + 5280;           // [20][264]
    float* s_w0 = st + 10560;          // 25
    float* s_w1 = st + 10592;          // 25

    int bx = blockIdx.x;               // 6144 = 16 * 96 * 4
    int yt = bx & 15;
    int v = bx >> 4;
    int c = v % 96, b = v / 96;
    int y0 = yt << 4;
    int tid = threadIdx.x;
    int chan = b * IMG + c * HW;
    const float* Vc  = g_V  + chan;
    const float* aVc = g_aV + chan;

    for (int l = tid; l < 5200; l += 256) {
        int r = l / 260, q = l - r * 260;
        int yy = y0 + r - 2; yy = yy < 0 ? -yy : (yy > 255 ? 510 - yy : yy);
        int xx = q - 2;      xx = xx < 0 ? -xx : (xx > 255 ? 510 - xx : xx);
        int ga = yy * 256 + xx;
        s_h0[r * 264 + q] = Vc[ga];
        s_h1[r * 264 + q] = aVc[ga];
    }
    if (tid < 25) { s_w0[tid] = wdw[c * 25 + tid]; s_w1[tid] = wdwa[c * 25 + tid]; }
    __syncthreads();

    int col = tid;
    float av[16];
    const float* ab = g_attn + chan + y0 * 256 + col;
    #pragma unroll
    for (int r = 0; r < 16; r++) av[r] = ab[r * 256];

    #pragma unroll
    for (int z = 0; z < 2; z++) {
        const float* sh = z ? s_h1 : s_h0;
        const float* sw = z ? s_w1 : s_w0;
        float bias = z ? __ldg(&bdwa[c]) : __ldg(&bdw[c]);
        float w[25];
        #pragma unroll
        for (int k = 0; k < 25; k++) w[k] = sw[k];

        float acc[16];
        #pragma unroll
        for (int r = 0; r < 16; r++) acc[r] = bias + av[r];

        #pragma unroll
        for (int rr = 0; rr < 20; rr++) {
            float xv[5];
            #pragma unroll
            for (int dx = 0; dx < 5; dx++) xv[dx] = sh[rr * 264 + col + dx];
            #pragma unroll
            for (int dy = 0; dy < 5; dy++) {
                int r = rr - dy;
                if (r >= 0 && r < 16) {
                    #pragma unroll
                    for (int dx = 0; dx < 5; dx++)
                        acc[r] = fmaf(xv[dx], w[dy * 5 + dx], acc[r]);
                }
            }
        }

        float* db = (z ? g_K : g_Q) + chan + y0 * 256 + col;
        #pragma unroll
        for (int r = 0; r < 16; r++)
            db[r * 256] = acc[r];
    }
}

// ---------------------------------------------------------------------------
extern "C" void kernel_launch(void* const* d_in, const int* in_sizes, int n_in,
                              void* d_out, int out_size) {
    const float* vision     = (const float*)d_in[0];
    const float* ass_vision = (const float*)d_in[1];
    const float* wv   = (const float*)d_in[2];
    const float* bv   = (const float*)d_in[3];
    const float* wav  = (const float*)d_in[4];
    const float* bav  = (const float*)d_in[5];
    const float* wqk  = (const float*)d_in[6];
    const float* bqk  = (const float*)d_in[7];
    // d_in[8..9]: waqk/baqk dead (reference bug: aaw unused, ass_attn_out = attn_out)
    const float* wdw  = (const float*)d_in[10];
    const float* bdw  = (const float*)d_in[11];
    const float* wdwa = (const float*)d_in[12];
    const float* bdwa = (const float*)d_in[13];
    const float* wp   = (const float*)d_in[14];
    const float* bp   = (const float*)d_in[15];
    const float* wpa  = (const float*)d_in[16];
    const float* bpa  = (const float*)d_in[17];
    const float* mw1  = (const float*)d_in[18];
    const float* mb1  = (const float*)d_in[19];
    const float* mw2  = (const float*)d_in[20];
    const float* mb2  = (const float*)d_in[21];
    float* out = (float*)d_out;

    float *pV, *paV, *pQ, *pK;
    cudaGetSymbolAddress((void**)&pV,  g_V);
    cudaGetSymbolAddress((void**)&paV, g_aV);
    cudaGetSymbolAddress((void**)&pQ,  g_Q);
    cudaGetSymbolAddress((void**)&pK,  g_K);

    const int SMEM_CONV = 6336 * 8 + 9312 * 4 + 96 * 4;   // 88320
    const int SMEM_ATTN = 19200 * 4;                       // 76800
    const int SMEM_DW   = 10624 * 4;                       // 42496
    cudaFuncSetAttribute(conv_kernel, cudaFuncAttributeMaxDynamicSharedMemorySize, SMEM_CONV);
    cudaFuncSetAttribute(attn_kernel, cudaFuncAttributeMaxDynamicSharedMemorySize, SMEM_ATTN);
    cudaFuncSetAttribute(dw_kernel,   cudaFuncAttributeMaxDynamicSharedMemorySize, SMEM_DW);

    bias_kernel<<<16, 256>>>(mw1, mb1, mw2, mb2);

    // V, Q (pre-scaled), K, aV: 4 independent jobs
    ConvJob jV  = { vision,     wv,         bv,       pV,  1.0f };
    ConvJob jQ  = { vision,     wqk,        bqk,      pQ,  SCALE };
    ConvJob jK  = { vision,     wqk + 9216, bqk + 96, pK,  1.0f };
    ConvJob jaV = { ass_vision, wav,        bav,      paV, 1.0f };
    conv_kernel<<<dim3(2048, 1, 4), 256, SMEM_CONV>>>(jV, jQ, jK, jaV);

    // window attention: 4096 windows, 192 threads (3 heads x 64 rows)
    attn_kernel<<<4096, 192, SMEM_ATTN>>>();

    // depthwise + attn add -> D0 (g_Q), D1 (g_K)
    dw_kernel<<<6144, 256, SMEM_DW>>>(wdw, bdw, wdwa, bdwa);

    // final projections
    ConvJob jP0 = { pQ, wp,  bp,  out,        1.0f };
    ConvJob jP1 = { pK, wpa, bpa, out + NPIX, 1.0f };
    conv_kernel<<<dim3(2048, 1, 2), 256, SMEM_CONV>>>(jP0, jP1, jP0, jP0);
}